// round 13
// baseline (speedup 1.0000x reference)
#include <cuda_runtime.h>
#include <cuda_bf16.h>
#include <cstdint>
#include <math.h>
#include <math_constants.h>

#define B_     8
#define NTOK   1024
#define DIM    512
#define HEADS  16
#define HD     32
#define TBL    3969
#define LOG2E  1.4426950408889634f
#define SMSHIFT 48.0f
#define HSZ    (B_ * HEADS * NTOK * HD)
#define ASZ    (B_ * NTOK * DIM)

typedef __nv_bfloat16 bf16;

// ---------------- scratch (device globals; no dynamic allocation) ----------
__device__ bf16  g_xhi[ASZ],            g_xlo[ASZ];
__device__ bf16  g_wqhi[3 * DIM * DIM], g_wqlo[3 * DIM * DIM];
__device__ bf16  g_wphi[DIM * DIM],     g_wplo[DIM * DIM];
__device__ bf16  g_Q2[2 * HSZ];         // Qhi | Qlo
__device__ bf16  g_KV[4 * HSZ];         // Khi | Klo | Vhi | Vlo
__device__ bf16  g_A2[2 * ASZ];         // attn out hi | lo
__device__ bf16  g_rb [HEADS * NTOK * NTOK];   // bias * log2e, fragment-major
__device__ float g_tt [HEADS * TBL];

// ---------------------------------------------------------------------------
// helpers
// ---------------------------------------------------------------------------
__device__ __forceinline__ void mma16(float* d, const unsigned* a, unsigned b0, unsigned b1) {
    asm volatile("mma.sync.aligned.m16n8k16.row.col.f32.bf16.bf16.f32 "
                 "{%0,%1,%2,%3}, {%4,%5,%6,%7}, {%8,%9}, {%0,%1,%2,%3};"
                 : "+f"(d[0]), "+f"(d[1]), "+f"(d[2]), "+f"(d[3])
                 : "r"(a[0]), "r"(a[1]), "r"(a[2]), "r"(a[3]), "r"(b0), "r"(b1));
}
__device__ __forceinline__ void ldsm_x4(unsigned& r0, unsigned& r1, unsigned& r2,
                                        unsigned& r3, unsigned addr) {
    asm volatile("ldmatrix.sync.aligned.m8n8.x4.shared.b16 {%0,%1,%2,%3}, [%4];"
                 : "=r"(r0), "=r"(r1), "=r"(r2), "=r"(r3) : "r"(addr));
}
__device__ __forceinline__ void ldsm_x4t(unsigned& r0, unsigned& r1, unsigned& r2,
                                         unsigned& r3, unsigned addr) {
    asm volatile("ldmatrix.sync.aligned.m8n8.x4.trans.shared.b16 {%0,%1,%2,%3}, [%4];"
                 : "=r"(r0), "=r"(r1), "=r"(r2), "=r"(r3) : "r"(addr));
}
__device__ __forceinline__ void cp16(uint32_t dst, const void* src) {
    asm volatile("cp.async.cg.shared.global [%0], [%1], 16;" :: "r"(dst), "l"(src));
}
#define CP_COMMIT() asm volatile("cp.async.commit_group;" ::: "memory")
#define CP_WAIT1()  asm volatile("cp.async.wait_group 1;" ::: "memory")
#define CP_WAIT0()  asm volatile("cp.async.wait_group 0;" ::: "memory")

__device__ __forceinline__ unsigned packbf(float a, float b) {
    __nv_bfloat162 h = __floats2bfloat162_rn(a, b);
    return *(unsigned*)&h;
}
__device__ __forceinline__ void splitf(float x, bf16& hi, bf16& lo) {
    hi = __float2bfloat16_rn(x);
    lo = __float2bfloat16_rn(x - __bfloat162float(hi));
}
__device__ __forceinline__ float ex2(float x) {
    float r;
    asm("ex2.approx.ftz.f32 %0, %1;" : "=f"(r) : "f"(x));
    return r;
}
__device__ __forceinline__ uint32_t smem_u32(const void* p) {
    return (uint32_t)__cvta_generic_to_shared(p);
}

// ---------------------------------------------------------------------------
// Kernel 0: fused prologue — three fp32->bf16 hi/lo splits + CPB MLP.
// ---------------------------------------------------------------------------
#define XBLK   (ASZ / 1024)
#define WQBLK  ((3 * DIM * DIM) / 1024)
#define WPBLK  ((DIM * DIM) / 1024)
#define SPLITBLK (XBLK + WQBLK + WPBLK)

__global__ __launch_bounds__(256)
void prologue_kernel(const float* __restrict__ x, const float* __restrict__ qkv_w,
                     const float* __restrict__ proj_w,
                     bf16* __restrict__ xhi, bf16* __restrict__ xlo,
                     bf16* __restrict__ wqhi, bf16* __restrict__ wqlo,
                     bf16* __restrict__ wphi, bf16* __restrict__ wplo,
                     const float* __restrict__ tbl, const float* __restrict__ w1,
                     const float* __restrict__ b1, const float* __restrict__ w2,
                     const float* __restrict__ b2, float* __restrict__ tt)
{
    const int bid = blockIdx.x;
    const int tid = threadIdx.x;
    if (bid < SPLITBLK) {
        const float* in;
        bf16 *hi, *lo;
        int base;
        if (bid < XBLK)              { in = x;      hi = xhi;  lo = xlo;  base = bid; }
        else if (bid < XBLK + WQBLK) { in = qkv_w;  hi = wqhi; lo = wqlo; base = bid - XBLK; }
        else                         { in = proj_w; hi = wphi; lo = wplo; base = bid - XBLK - WQBLK; }
        const int i = base * 1024 + tid * 4;
        const float4 v = *(const float4*)(in + i);
        bf16 h0, h1, h2, h3, l0, l1, l2, l3;
        splitf(v.x, h0, l0); splitf(v.y, h1, l1);
        splitf(v.z, h2, l2); splitf(v.w, h3, l3);
        ((uint2*)hi)[i >> 2] = make_uint2(packbf(__bfloat162float(h0), __bfloat162float(h1)),
                                          packbf(__bfloat162float(h2), __bfloat162float(h3)));
        ((uint2*)lo)[i >> 2] = make_uint2(packbf(__bfloat162float(l0), __bfloat162float(l1)),
                                          packbf(__bfloat162float(l2), __bfloat162float(l3)));
        return;
    }
    const int r = bid - SPLITBLK;
    __shared__ float hid[512];
    const float c0 = tbl[r * 2 + 0];
    const float c1 = tbl[r * 2 + 1];
    hid[tid]       = fmaxf(fmaf(c0, w1[tid * 2 + 0],
                           fmaf(c1, w1[tid * 2 + 1], b1[tid])), 0.0f);
    hid[tid + 256] = fmaxf(fmaf(c0, w1[(tid + 256) * 2 + 0],
                           fmaf(c1, w1[(tid + 256) * 2 + 1], b1[tid + 256])), 0.0f);
    __syncthreads();
    const int w = tid >> 5, lane = tid & 31;
#pragma unroll
    for (int hh = 0; hh < 2; hh++) {
        const int h = w * 2 + hh;
        float s = 0.0f;
#pragma unroll
        for (int i = 0; i < 512; i += 32)
            s = fmaf(hid[i + lane], w2[h * 512 + i + lane], s);
#pragma unroll
        for (int msk = 16; msk >= 1; msk >>= 1)
            s += __shfl_xor_sync(0xffffffffu, s, msk);
        if (lane == 0)
            tt[h * TBL + r] = s + b2[h];
    }
}

// ---------------------------------------------------------------------------
// Kernel 1: qkv GEMM (3xBF16, 128x128, k-step 32) + fused norm/split
// epilogue (merged-plane outputs) + trailing rb blocks (tail fill).
// ---------------------------------------------------------------------------
#define GBUF 40960
#define GROW 40
#define RB_YBASE 64

__global__ __launch_bounds__(256, 2)
void gemm_qkv(const bf16* __restrict__ Ahi, const bf16* __restrict__ Alo,
              const bf16* __restrict__ Bhi, const bf16* __restrict__ Blo,
              const float* __restrict__ bias,
              int M, int N, int K,
              const float* __restrict__ temp, const float* __restrict__ qe,
              const float* __restrict__ sls,
              bf16* __restrict__ Q2, bf16* __restrict__ KV,
              const int* __restrict__ idx, const float* __restrict__ tt,
              bf16* __restrict__ rbout)
{
    extern __shared__ __align__(16) char smraw[];
    const uint32_t smb = smem_u32(smraw);
    const int tid = threadIdx.x;

    if (blockIdx.y >= RB_YBASE) {
        const int q = (blockIdx.y - RB_YBASE) * 12 + blockIdx.x;
        if (q >= NTOK) return;
        int* idxbuf = (int*)smraw;
        ((int4*)idxbuf)[tid] = ((const int4*)(idx + q * NTOK))[tid];
        __syncthreads();
        const int kp = tid * 4;
        const int blk = kp & ~63;
        const int j = kp & 63;
        const int tig = j >> 4;
        const int nt0 = (j & 15) >> 1;
        const int2 i0 = *(const int2*)&idxbuf[blk + nt0 * 8 + 2 * tig];
        const int2 i1 = *(const int2*)&idxbuf[blk + (nt0 + 1) * 8 + 2 * tig];
#pragma unroll 4
        for (int h = 0; h < HEADS; h++) {
            const float* tth = tt + h * TBL;
            ((uint2*)rbout)[(((size_t)h * NTOK + q) * NTOK + kp) >> 2] =
                make_uint2(packbf(tth[i0.x] * LOG2E, tth[i0.y] * LOG2E),
                           packbf(tth[i1.x] * LOG2E, tth[i1.y] * LOG2E));
        }
        return;
    }

    const int w = tid >> 5, lane = tid & 31;
    const int gid = lane >> 2, tig = lane & 3;
    const int wm = w >> 2, wn = w & 3;
    const int row0 = blockIdx.y * 128, col0 = blockIdx.x * 128;
    const int NS = K / 32;

    const int rowA = (lane & 7) | (lane & 8);
    const uint32_t aoff = (uint32_t)(rowA * GROW + ((lane & 16) >> 1)) * 2;
    const int rowB = (lane & 7) | ((lane & 16) >> 1);
    const uint32_t boff = (uint32_t)(rowB * GROW + (lane & 8)) * 2;

    float acc[4][4][4];
#pragma unroll
    for (int i = 0; i < 4; i++)
#pragma unroll
        for (int j = 0; j < 4; j++)
#pragma unroll
            for (int q = 0; q < 4; q++) acc[i][j][q] = 0.0f;

#define GEMM_LOAD(s, buf)                                                          \
    {                                                                              \
        const int k0_ = (s) * 32;                                                  \
        _Pragma("unroll")                                                          \
        for (int i_ = 0; i_ < 2; i_++) {                                           \
            const int slot_ = tid + i_ * 256;                                      \
            const int r_ = slot_ >> 2, q_ = slot_ & 3;                             \
            const uint32_t d_ = smb + (buf) * GBUF + (uint32_t)(r_ * 80 + q_ * 16);\
            const size_t ga_ = (size_t)(row0 + r_) * K + k0_ + q_ * 8;             \
            const size_t gb_ = (size_t)(col0 + r_) * K + k0_ + q_ * 8;             \
            cp16(d_,         Ahi + ga_);                                           \
            cp16(d_ + 10240, Alo + ga_);                                           \
            cp16(d_ + 20480, Bhi + gb_);                                           \
            cp16(d_ + 30720, Blo + gb_);                                           \
        }                                                                          \
        CP_COMMIT();                                                               \
    }

    GEMM_LOAD(0, 0);
    GEMM_LOAD(1, 1);

    for (int s = 0; s < NS; s++) {
        if (s < NS - 1) { CP_WAIT1(); } else { CP_WAIT0(); }
        __syncthreads();
        const uint32_t base = smb + (s & 1) * GBUF;
#pragma unroll
        for (int kt = 0; kt < 2; kt++) {
            unsigned bh[4][2], bl[4][2];
#pragma unroll
            for (int ntp = 0; ntp < 2; ntp++) {
                const uint32_t ba = base + 20480 + boff
                                  + (uint32_t)((wn * 32 + ntp * 16) * 80 + kt * 32);
                ldsm_x4(bh[2*ntp][0], bh[2*ntp][1], bh[2*ntp+1][0], bh[2*ntp+1][1], ba);
                ldsm_x4(bl[2*ntp][0], bl[2*ntp][1], bl[2*ntp+1][0], bl[2*ntp+1][1], ba + 10240);
            }
#pragma unroll
            for (int mt = 0; mt < 4; mt++) {
                const uint32_t aa = base + aoff
                                  + (uint32_t)((wm * 64 + mt * 16) * 80 + kt * 32);
                unsigned ah[4], al[4];
                ldsm_x4(ah[0], ah[1], ah[2], ah[3], aa);
                ldsm_x4(al[0], al[1], al[2], al[3], aa + 10240);
#pragma unroll
                for (int nt = 0; nt < 4; nt++) {
                    mma16(acc[mt][nt], ah, bh[nt][0], bh[nt][1]);
                    mma16(acc[mt][nt], al, bh[nt][0], bh[nt][1]);
                    mma16(acc[mt][nt], ah, bl[nt][0], bl[nt][1]);
                }
            }
        }
        __syncthreads();
        if (s + 2 < NS) GEMM_LOAD(s + 2, s & 1);
    }

    // ---- fused qkv epilogue (merged-plane destinations)
    const int cb = col0 + wn * 32;
    const int region = cb >> 9;
    const int h = (cb >> 5) & 15;
    float qscale = 0.0f;
    if (region == 0)
        qscale = log1pf(expf(temp[h])) * sls[0] * LOG2E;
    float bb[4][2];
    float qev[4][2];
#pragma unroll
    for (int nt = 0; nt < 4; nt++) {
        const int c = cb + nt * 8 + 2 * tig;
        bb[nt][0] = bias[c]; bb[nt][1] = bias[c + 1];
        if (region == 0) {
            qev[nt][0] = qe[h * HD + (c & 31)];
            qev[nt][1] = qe[h * HD + ((c + 1) & 31)];
        }
    }
    bf16* dsthi = (region == 0) ? Q2 : (region == 1) ? KV : (KV + 2 * (size_t)HSZ);
    bf16* dstlo = dsthi + HSZ;

#pragma unroll
    for (int mt = 0; mt < 4; mt++) {
#pragma unroll
        for (int half = 0; half < 2; half++) {
            const int r = row0 + wm * 64 + mt * 16 + gid + half * 8;
            const int b = r >> 10, n = r & 1023;
            float v[4][2];
            float s2 = 0.0f;
#pragma unroll
            for (int nt = 0; nt < 4; nt++) {
                v[nt][0] = acc[mt][nt][2 * half + 0] + bb[nt][0];
                v[nt][1] = acc[mt][nt][2 * half + 1] + bb[nt][1];
                s2 = fmaf(v[nt][0], v[nt][0], fmaf(v[nt][1], v[nt][1], s2));
            }
            if (region < 2) {
                s2 += __shfl_xor_sync(0xffffffffu, s2, 1);
                s2 += __shfl_xor_sync(0xffffffffu, s2, 2);
                const float inv = 1.0f / fmaxf(sqrtf(s2), 1e-12f);
#pragma unroll
                for (int nt = 0; nt < 4; nt++) {
                    if (region == 0) {
                        v[nt][0] = (v[nt][0] * inv + qev[nt][0]) * qscale;
                        v[nt][1] = (v[nt][1] * inv + qev[nt][1]) * qscale;
                    } else {
                        v[nt][0] *= inv;
                        v[nt][1] *= inv;
                    }
                }
            }
            const size_t obase = ((((size_t)b * HEADS + h) << 10) + n) * HD;
#pragma unroll
            for (int nt = 0; nt < 4; nt++) {
                const int d = nt * 8 + 2 * tig;
                bf16 h0, l0, h1, l1;
                splitf(v[nt][0], h0, l0);
                splitf(v[nt][1], h1, l1);
                ((unsigned*)dsthi)[(obase + d) >> 1] =
                    packbf(__bfloat162float(h0), __bfloat162float(h1));
                ((unsigned*)dstlo)[(obase + d) >> 1] =
                    packbf(__bfloat162float(l0), __bfloat162float(l1));
            }
        }
    }
}

// ---------------------------------------------------------------------------
// Kernel 3: proj GEMM — 128x128 tiles, 2 CTA/SM (known-best config).
// ---------------------------------------------------------------------------
__global__ __launch_bounds__(256, 2)
void gemm_proj(const bf16* __restrict__ Ahi, const bf16* __restrict__ Alo,
               const bf16* __restrict__ Bhi, const bf16* __restrict__ Blo,
               const float* __restrict__ bias, float* __restrict__ C,
               int M, int N, int K)
{
    extern __shared__ __align__(16) char smraw[];
    const uint32_t smb = smem_u32(smraw);
    const int tid = threadIdx.x;
    const int w = tid >> 5, lane = tid & 31;
    const int gid = lane >> 2, tig = lane & 3;
    const int wm = w >> 2, wn = w & 3;
    const int row0 = blockIdx.y * 128, col0 = blockIdx.x * 128;
    const int NS = K / 32;

    const int rowA = (lane & 7) | (lane & 8);
    const uint32_t aoff = (uint32_t)(rowA * GROW + ((lane & 16) >> 1)) * 2;
    const int rowB = (lane & 7) | ((lane & 16) >> 1);
    const uint32_t boff = (uint32_t)(rowB * GROW + (lane & 8)) * 2;

    float acc[4][4][4];
#pragma unroll
    for (int i = 0; i < 4; i++)
#pragma unroll
        for (int j = 0; j < 4; j++)
#pragma unroll
            for (int q = 0; q < 4; q++) acc[i][j][q] = 0.0f;

    GEMM_LOAD(0, 0);
    GEMM_LOAD(1, 1);

    for (int s = 0; s < NS; s++) {
        if (s < NS - 1) { CP_WAIT1(); } else { CP_WAIT0(); }
        __syncthreads();
        const uint32_t base = smb + (s & 1) * GBUF;
#pragma unroll
        for (int kt = 0; kt < 2; kt++) {
            unsigned bh[4][2], bl[4][2];
#pragma unroll
            for (int ntp = 0; ntp < 2; ntp++) {
                const uint32_t ba = base + 20480 + boff
                                  + (uint32_t)((wn * 32 + ntp * 16) * 80 + kt * 32);
                ldsm_x4(bh[2*ntp][0], bh[2*ntp][1], bh[2*ntp+1][0], bh[2*ntp+1][1], ba);
                ldsm_x4(bl[2*ntp][0], bl[2*ntp][1], bl[2*ntp+1][0], bl[2*ntp+1][1], ba + 10240);
            }
#pragma unroll
            for (int mt = 0; mt < 4; mt++) {
                const uint32_t aa = base + aoff
                                  + (uint32_t)((wm * 64 + mt * 16) * 80 + kt * 32);
                unsigned ah[4], al[4];
                ldsm_x4(ah[0], ah[1], ah[2], ah[3], aa);
                ldsm_x4(al[0], al[1], al[2], al[3], aa + 10240);
#pragma unroll
                for (int nt = 0; nt < 4; nt++) {
                    mma16(acc[mt][nt], ah, bh[nt][0], bh[nt][1]);
                    mma16(acc[mt][nt], al, bh[nt][0], bh[nt][1]);
                    mma16(acc[mt][nt], ah, bl[nt][0], bl[nt][1]);
                }
            }
        }
        __syncthreads();
        if (s + 2 < NS) GEMM_LOAD(s + 2, s & 1);
    }

#pragma unroll
    for (int mt = 0; mt < 4; mt++) {
        const int ra = row0 + wm * 64 + mt * 16 + gid;
#pragma unroll
        for (int nt = 0; nt < 4; nt++) {
            const int c = col0 + wn * 32 + nt * 8 + 2 * tig;
            const float bb0 = bias[c], bb1 = bias[c + 1];
            *(float2*)(C + (size_t)ra * N + c) =
                make_float2(acc[mt][nt][0] + bb0, acc[mt][nt][1] + bb1);
            *(float2*)(C + (size_t)(ra + 8) * N + c) =
                make_float2(acc[mt][nt][2] + bb0, acc[mt][nt][3] + bb1);
        }
    }
}

// ---------------------------------------------------------------------------
// Kernel 2: bf16-split flash attention — round-8 body, 512 threads / q-tile
// 256. Each 64-key K/V stage is consumed by 16 warps (2x amortization of
// smem broadcast traffic). 2-stage cp.async ring: threads 0-255 load K
// planes, 256-511 load V planes. Fixed-offset softmax, register-direct P.
// ---------------------------------------------------------------------------
#define KROW 40
#define KPS  (64 * KROW * 2)
#define STG  (4 * KPS)
#define ATTN_SMEM (2 * STG)       // 40960

__global__ __launch_bounds__(512, 1)
void attn_mma(const bf16* __restrict__ Q2, const bf16* __restrict__ KV,
              const bf16* __restrict__ rb, bf16* __restrict__ aout)
{
    extern __shared__ __align__(16) char smraw[];
    const uint32_t smb = smem_u32(smraw);

    const int tid = threadIdx.x;
    const int w = tid >> 5, lane = tid & 31;
    const int gid = lane >> 2, tig = lane & 3;
    const int b = blockIdx.x, h = blockIdx.y, q0 = blockIdx.z * 256;
    const size_t bh = ((size_t)b * HEADS + h) * NTOK * HD;
    const bf16* KVg = KV + bh;
    const bf16* rbh = rb + (size_t)h * NTOK * NTOK;
    const int r0 = q0 + w * 16 + gid;
    const int r1 = r0 + 8;

    const uint32_t koff = (uint32_t)((((lane & 7) | ((lane & 16) >> 1)) * KROW + (lane & 8)) * 2);
    const uint32_t voff = (uint32_t)((((lane & 7) | (lane & 8)) * KROW + ((lane & 16) >> 1)) * 2);

    unsigned qh[2][4], ql[2][4];
#pragma unroll
    for (int kt = 0; kt < 2; kt++) {
        const int d0 = kt * 16 + 2 * tig;
        qh[kt][0] = *(const unsigned*)(Q2 + bh + (size_t)r0 * HD + d0);
        qh[kt][1] = *(const unsigned*)(Q2 + bh + (size_t)r1 * HD + d0);
        qh[kt][2] = *(const unsigned*)(Q2 + bh + (size_t)r0 * HD + d0 + 8);
        qh[kt][3] = *(const unsigned*)(Q2 + bh + (size_t)r1 * HD + d0 + 8);
        ql[kt][0] = *(const unsigned*)(Q2 + HSZ + bh + (size_t)r0 * HD + d0);
        ql[kt][1] = *(const unsigned*)(Q2 + HSZ + bh + (size_t)r1 * HD + d0);
        ql[kt][2] = *(const unsigned*)(Q2 + HSZ + bh + (size_t)r0 * HD + d0 + 8);
        ql[kt][3] = *(const unsigned*)(Q2 + HSZ + bh + (size_t)r1 * HD + d0 + 8);
    }

    float o[4][4];
#pragma unroll
    for (int i = 0; i < 4; i++)
#pragma unroll
        for (int j = 0; j < 4; j++) o[i][j] = 0.0f;
    float l0 = 0.0f, l1 = 0.0f;

    // threads 0-255: K hi/lo planes; threads 256-511: V hi/lo planes
#define ATTN_LOAD(t, buf)                                                      \
    {                                                                          \
        const int half_ = tid >> 8;                                            \
        const int t2_ = tid & 255;                                             \
        const int r_ = t2_ >> 2, q_ = t2_ & 3;                                 \
        const uint32_t d_ = smb + (buf) * STG                                  \
                          + (uint32_t)(half_ * 2 * KPS + r_ * 80 + q_ * 16);   \
        const size_t g_ = (size_t)((t) * 64 + r_) * HD + q_ * 8;               \
        const bf16* s0_ = KVg + (half_ ? 2 * (size_t)HSZ : 0) + g_;            \
        cp16(d_,       s0_);                                                   \
        cp16(d_ + KPS, s0_ + HSZ);                                             \
        CP_COMMIT();                                                           \
    }

    ATTN_LOAD(0, 0);

    for (int t = 0; t < 16; t++) {
        if (t < 15) ATTN_LOAD(t + 1, (t + 1) & 1);
        const int key0 = t * 64;

        // gathered bias (fragment-major): 4 x 16B loads cover the whole tile
        float s[8][4];
        {
            const bf16* rp0 = rbh + ((size_t)r0 << 10) + key0 + tig * 16;
            const bf16* rp1 = rbh + ((size_t)r1 << 10) + key0 + tig * 16;
            const uint4 Ua = *(const uint4*)rp0;
            const uint4 Ub = *(const uint4*)(rp0 + 8);
            const uint4 Uc = *(const uint4*)rp1;
            const uint4 Ud = *(const uint4*)(rp1 + 8);
            const unsigned pr0[8] = {Ua.x, Ua.y, Ua.z, Ua.w, Ub.x, Ub.y, Ub.z, Ub.w};
            const unsigned pr1[8] = {Uc.x, Uc.y, Uc.z, Uc.w, Ud.x, Ud.y, Ud.z, Ud.w};
#pragma unroll
            for (int nt = 0; nt < 8; nt++) {
                const float2 f0 = __bfloat1622float2(*(const __nv_bfloat162*)&pr0[nt]);
                const float2 f1 = __bfloat1622float2(*(const __nv_bfloat162*)&pr1[nt]);
                s[nt][0] = f0.x; s[nt][1] = f0.y; s[nt][2] = f1.x; s[nt][3] = f1.y;
            }
        }

        if (t < 15) { CP_WAIT1(); } else { CP_WAIT0(); }
        __syncthreads();
        const uint32_t base = smb + (t & 1) * STG;

        // ---- S += Q K^T (3xBF16)
#pragma unroll
        for (int kt = 0; kt < 2; kt++) {
#pragma unroll
            for (int ntp = 0; ntp < 4; ntp++) {
                const uint32_t ka = base + koff + (uint32_t)(ntp * 1280 + kt * 32);
                unsigned kh0, kh1, kh2, kh3, kl0, kl1, kl2, kl3;
                ldsm_x4(kh0, kh1, kh2, kh3, ka);
                ldsm_x4(kl0, kl1, kl2, kl3, ka + KPS);
                mma16(s[2*ntp],   qh[kt], kh0, kh1);
                mma16(s[2*ntp],   ql[kt], kh0, kh1);
                mma16(s[2*ntp],   qh[kt], kl0, kl1);
                mma16(s[2*ntp+1], qh[kt], kh2, kh3);
                mma16(s[2*ntp+1], ql[kt], kh2, kh3);
                mma16(s[2*ntp+1], qh[kt], kl2, kl3);
            }
        }

        // ---- fixed-offset softmax (bias was accumulator init)
#pragma unroll
        for (int nt = 0; nt < 8; nt++) {
            s[nt][0] = ex2(s[nt][0] - SMSHIFT);
            s[nt][1] = ex2(s[nt][1] - SMSHIFT);
            s[nt][2] = ex2(s[nt][2] - SMSHIFT);
            s[nt][3] = ex2(s[nt][3] - SMSHIFT);
            l0 += s[nt][0] + s[nt][1];
            l1 += s[nt][2] + s[nt][3];
        }

        // ---- O += P V: V ldsm issued FIRST, then register-direct P packs
#pragma unroll
        for (int kt = 0; kt < 4; kt++) {
            unsigned vh[8], vl[8];
#pragma unroll
            for (int ntp = 0; ntp < 2; ntp++) {
                const uint32_t va = base + 2 * KPS + voff + (uint32_t)(kt * 1280 + ntp * 32);
                ldsm_x4t(vh[4*ntp], vh[4*ntp+1], vh[4*ntp+2], vh[4*ntp+3], va);
                ldsm_x4t(vl[4*ntp], vl[4*ntp+1], vl[4*ntp+2], vl[4*ntp+3], va + KPS);
            }
            unsigned ph[4], pl[4];
#pragma unroll
            for (int half = 0; half < 2; half++) {
                const int nt = 2 * kt + half;
                const unsigned h01 = packbf(s[nt][0], s[nt][1]);
                const unsigned h23 = packbf(s[nt][2], s[nt][3]);
                const float2 f01 = __bfloat1622float2(*(const __nv_bfloat162*)&h01);
                const float2 f23 = __bfloat1622float2(*(const __nv_bfloat162*)&h23);
                ph[2 * half + 0] = h01;
                ph[2 * half + 1] = h23;
                pl[2 * half + 0] = packbf(s[nt][0] - f01.x, s[nt][1] - f01.y);
                pl[2 * half + 1] = packbf(s[nt][2] - f23.x, s[nt][3] - f23.y);
            }
#pragma unroll
            for (int ntp = 0; ntp < 2; ntp++) {
                mma16(o[2*ntp],   ph, vh[4*ntp+0], vh[4*ntp+1]);
                mma16(o[2*ntp],   pl, vh[4*ntp+0], vh[4*ntp+1]);
                mma16(o[2*ntp],   ph, vl[4*ntp+0], vl[4*ntp+1]);
                mma16(o[2*ntp+1], ph, vh[4*ntp+2], vh[4*ntp+3]);
                mma16(o[2*ntp+1], pl, vh[4*ntp+2], vh[4*ntp+3]);
                mma16(o[2*ntp+1], ph, vl[4*ntp+2], vl[4*ntp+3]);
            }
        }
        __syncthreads();
    }

    l0 += __shfl_xor_sync(0xffffffffu, l0, 1);
    l0 += __shfl_xor_sync(0xffffffffu, l0, 2);
    l1 += __shfl_xor_sync(0xffffffffu, l1, 1);
    l1 += __shfl_xor_sync(0xffffffffu, l1, 2);

    const float inv0 = 1.0f / l0, inv1 = 1.0f / l1;
#pragma unroll
    for (int dnt = 0; dnt < 4; dnt++) {
        const int c = h * HD + dnt * 8 + 2 * tig;
        {
            const float v0 = o[dnt][0] * inv0, v1 = o[dnt][1] * inv0;
            const float h0 = __bfloat162float(__float2bfloat16_rn(v0));
            const float h1 = __bfloat162float(__float2bfloat16_rn(v1));
            const size_t u = ((size_t)(((size_t)b << 10) + r0) * DIM + c) >> 1;
            ((unsigned*)aout)[u] = packbf(v0, v1);
            ((unsigned*)(aout + ASZ))[u] = packbf(v0 - h0, v1 - h1);
        }
        {
            const float v0 = o[dnt][2] * inv1, v1 = o[dnt][3] * inv1;
            const float h0 = __bfloat162float(__float2bfloat16_rn(v0));
            const float h1 = __bfloat162float(__float2bfloat16_rn(v1));
            const size_t u = ((size_t)(((size_t)b << 10) + r1) * DIM + c) >> 1;
            ((unsigned*)aout)[u] = packbf(v0, v1);
            ((unsigned*)(aout + ASZ))[u] = packbf(v0 - h0, v1 - h1);
        }
    }
}

// ---------------------------------------------------------------------------
extern "C" void kernel_launch(void* const* d_in, const int* in_sizes, int n_in,
                              void* d_out, int out_size)
{
    (void)in_sizes; (void)n_in; (void)out_size;
    const float* x      = (const float*)d_in[0];
    const float* qkv_w  = (const float*)d_in[1];
    const float* qkv_b  = (const float*)d_in[2];
    const float* proj_w = (const float*)d_in[3];
    const float* proj_b = (const float*)d_in[4];
    const float* temp   = (const float*)d_in[5];
    const float* qe     = (const float*)d_in[6];
    const float* c1w    = (const float*)d_in[7];
    const float* c1b    = (const float*)d_in[8];
    const float* c2w    = (const float*)d_in[9];
    const float* c2b    = (const float*)d_in[10];
    const float* rct    = (const float*)d_in[11];
    const int*   rpi    = (const int*)d_in[12];
    const float* sls    = (const float*)d_in[13];
    float* out = (float*)d_out;

    float *tt_s;
    bf16 *xhi, *xlo, *wqhi, *wqlo, *wphi, *wplo;
    bf16 *Q2, *KVp, *A2, *rb_s;
    cudaGetSymbolAddress((void**)&tt_s,  g_tt);
    cudaGetSymbolAddress((void**)&xhi,  g_xhi);  cudaGetSymbolAddress((void**)&xlo,  g_xlo);
    cudaGetSymbolAddress((void**)&wqhi, g_wqhi); cudaGetSymbolAddress((void**)&wqlo, g_wqlo);
    cudaGetSymbolAddress((void**)&wphi, g_wphi); cudaGetSymbolAddress((void**)&wplo, g_wplo);
    cudaGetSymbolAddress((void**)&Q2,  g_Q2);
    cudaGetSymbolAddress((void**)&KVp, g_KV);
    cudaGetSymbolAddress((void**)&A2,  g_A2);
    cudaGetSymbolAddress((void**)&rb_s, g_rb);

    cudaFuncSetAttribute(attn_mma, cudaFuncAttributeMaxDynamicSharedMemorySize, ATTN_SMEM);
    cudaFuncSetAttribute(gemm_qkv, cudaFuncAttributeMaxDynamicSharedMemorySize, 2 * GBUF);
    cudaFuncSetAttribute(gemm_proj, cudaFuncAttributeMaxDynamicSharedMemorySize, 2 * GBUF);

    // 0. fused prologue: splits + CPB MLP
    prologue_kernel<<<SPLITBLK + TBL, 256>>>(
        x, qkv_w, proj_w, xhi, xlo, wqhi, wqlo, wphi, wplo,
        rct, c1w, c1b, c2w, c2b, tt_s);

    // 1. qkv projection (fused norm/split epilogue) + trailing rb blocks
    gemm_qkv<<<dim3(12, RB_YBASE + 86), 256, 2 * GBUF>>>(
        xhi, xlo, wqhi, wqlo, qkv_b, B_ * NTOK, 3 * DIM, DIM,
        temp, qe, sls, Q2, KVp, rpi, tt_s, rb_s);

    // 2. fused attention (512 threads, q-tile 256 — 2x K/V amortization)
    attn_mma<<<dim3(B_, HEADS, NTOK / 256), 512, ATTN_SMEM>>>(Q2, KVp, rb_s, A2);

    // 3. output projection (128x128 tiles, known-best config)
    gemm_proj<<<dim3(4, 64), 256, 2 * GBUF>>>(
        A2, A2 + ASZ, wphi, wplo, proj_b, out, B_ * NTOK, DIM, DIM);
}

// round 14
// speedup vs baseline: 1.1239x; 1.1239x over previous
#include <cuda_runtime.h>
#include <cuda_bf16.h>
#include <cstdint>
#include <math.h>
#include <math_constants.h>

#define B_     8
#define NTOK   1024
#define DIM    512
#define HEADS  16
#define HD     32
#define TBL    3969
#define LOG2E  1.4426950408889634f
#define SMSHIFT 48.0f

typedef __nv_bfloat16 bf16;

// ---------------- scratch (device globals; no dynamic allocation) ----------
__device__ bf16  g_xhi[B_ * NTOK * DIM],        g_xlo[B_ * NTOK * DIM];
__device__ bf16  g_wqhi[3 * DIM * DIM],         g_wqlo[3 * DIM * DIM];
__device__ bf16  g_wphi[DIM * DIM],             g_wplo[DIM * DIM];
__device__ bf16  g_Qhi[B_ * HEADS * NTOK * HD], g_Qlo[B_ * HEADS * NTOK * HD];
__device__ bf16  g_Khi[B_ * HEADS * NTOK * HD], g_Klo[B_ * HEADS * NTOK * HD];
__device__ bf16  g_Vhi[B_ * HEADS * NTOK * HD], g_Vlo[B_ * HEADS * NTOK * HD];
__device__ bf16  g_ahi[B_ * NTOK * DIM],        g_alo[B_ * NTOK * DIM];
__device__ bf16  g_rb [HEADS * NTOK * NTOK];    // bias * log2e, fragment-major permuted
__device__ float g_tt [HEADS * TBL];

// ---------------------------------------------------------------------------
// helpers
// ---------------------------------------------------------------------------
__device__ __forceinline__ void mma16(float* d, const unsigned* a, unsigned b0, unsigned b1) {
    asm volatile("mma.sync.aligned.m16n8k16.row.col.f32.bf16.bf16.f32 "
                 "{%0,%1,%2,%3}, {%4,%5,%6,%7}, {%8,%9}, {%0,%1,%2,%3};"
                 : "+f"(d[0]), "+f"(d[1]), "+f"(d[2]), "+f"(d[3])
                 : "r"(a[0]), "r"(a[1]), "r"(a[2]), "r"(a[3]), "r"(b0), "r"(b1));
}
__device__ __forceinline__ void ldsm_x4(unsigned& r0, unsigned& r1, unsigned& r2,
                                        unsigned& r3, unsigned addr) {
    asm volatile("ldmatrix.sync.aligned.m8n8.x4.shared.b16 {%0,%1,%2,%3}, [%4];"
                 : "=r"(r0), "=r"(r1), "=r"(r2), "=r"(r3) : "r"(addr));
}
__device__ __forceinline__ void ldsm_x4t(unsigned& r0, unsigned& r1, unsigned& r2,
                                         unsigned& r3, unsigned addr) {
    asm volatile("ldmatrix.sync.aligned.m8n8.x4.trans.shared.b16 {%0,%1,%2,%3}, [%4];"
                 : "=r"(r0), "=r"(r1), "=r"(r2), "=r"(r3) : "r"(addr));
}
__device__ __forceinline__ void cp16(uint32_t dst, const void* src) {
    asm volatile("cp.async.cg.shared.global [%0], [%1], 16;" :: "r"(dst), "l"(src));
}
#define CP_COMMIT() asm volatile("cp.async.commit_group;" ::: "memory")
#define CP_WAIT1()  asm volatile("cp.async.wait_group 1;" ::: "memory")
#define CP_WAIT0()  asm volatile("cp.async.wait_group 0;" ::: "memory")

__device__ __forceinline__ unsigned packbf(float a, float b) {
    __nv_bfloat162 h = __floats2bfloat162_rn(a, b);
    return *(unsigned*)&h;
}
__device__ __forceinline__ void splitf(float x, bf16& hi, bf16& lo) {
    hi = __float2bfloat16_rn(x);
    lo = __float2bfloat16_rn(x - __bfloat162float(hi));
}
__device__ __forceinline__ float ex2(float x) {
    float r;
    asm("ex2.approx.ftz.f32 %0, %1;" : "=f"(r) : "f"(x));
    return r;
}
__device__ __forceinline__ uint32_t smem_u32(const void* p) {
    return (uint32_t)__cvta_generic_to_shared(p);
}

// ---------------------------------------------------------------------------
// Kernel 0: fused prologue — three fp32->bf16 hi/lo splits + CPB MLP
// (8 table rows per block: w2 re-reads hit L1, 8x less L2 traffic).
// ---------------------------------------------------------------------------
#define XELEM  (B_ * NTOK * DIM)
#define WQELEM (3 * DIM * DIM)
#define WPELEM (DIM * DIM)
#define XBLK   (XELEM / 1024)
#define WQBLK  (WQELEM / 1024)
#define WPBLK  (WPELEM / 1024)
#define SPLITBLK (XBLK + WQBLK + WPBLK)
#define CPB_RPB 8
#define CPBBLK ((TBL + CPB_RPB - 1) / CPB_RPB)    // 497

__global__ __launch_bounds__(256)
void prologue_kernel(const float* __restrict__ x, const float* __restrict__ qkv_w,
                     const float* __restrict__ proj_w,
                     bf16* __restrict__ xhi, bf16* __restrict__ xlo,
                     bf16* __restrict__ wqhi, bf16* __restrict__ wqlo,
                     bf16* __restrict__ wphi, bf16* __restrict__ wplo,
                     const float* __restrict__ tbl, const float* __restrict__ w1,
                     const float* __restrict__ b1, const float* __restrict__ w2,
                     const float* __restrict__ b2, float* __restrict__ tt)
{
    const int bid = blockIdx.x;
    const int tid = threadIdx.x;
    if (bid < SPLITBLK) {
        const float* in;
        bf16 *hi, *lo;
        int base;
        if (bid < XBLK)              { in = x;      hi = xhi;  lo = xlo;  base = bid; }
        else if (bid < XBLK + WQBLK) { in = qkv_w;  hi = wqhi; lo = wqlo; base = bid - XBLK; }
        else                         { in = proj_w; hi = wphi; lo = wplo; base = bid - XBLK - WQBLK; }
        const int i = base * 1024 + tid * 4;
        const float4 v = *(const float4*)(in + i);
        bf16 h0, h1, h2, h3, l0, l1, l2, l3;
        splitf(v.x, h0, l0); splitf(v.y, h1, l1);
        splitf(v.z, h2, l2); splitf(v.w, h3, l3);
        ((uint2*)hi)[i >> 2] = make_uint2(packbf(__bfloat162float(h0), __bfloat162float(h1)),
                                          packbf(__bfloat162float(h2), __bfloat162float(h3)));
        ((uint2*)lo)[i >> 2] = make_uint2(packbf(__bfloat162float(l0), __bfloat162float(l1)),
                                          packbf(__bfloat162float(l2), __bfloat162float(l3)));
        return;
    }
    // ---- CPB MLP: this block handles rows [r0b, r0b + 8)
    const int r0b = (bid - SPLITBLK) * CPB_RPB;
    __shared__ float hid[512];
    const int w = tid >> 5, lane = tid & 31;
#pragma unroll
    for (int rr = 0; rr < CPB_RPB; rr++) {
        const int r = r0b + rr;
        if (r >= TBL) break;
        const float c0 = tbl[r * 2 + 0];
        const float c1 = tbl[r * 2 + 1];
        hid[tid]       = fmaxf(fmaf(c0, w1[tid * 2 + 0],
                               fmaf(c1, w1[tid * 2 + 1], b1[tid])), 0.0f);
        hid[tid + 256] = fmaxf(fmaf(c0, w1[(tid + 256) * 2 + 0],
                               fmaf(c1, w1[(tid + 256) * 2 + 1], b1[tid + 256])), 0.0f);
        __syncthreads();
#pragma unroll
        for (int hh = 0; hh < 2; hh++) {
            const int h = w * 2 + hh;
            float s = 0.0f;
#pragma unroll
            for (int i = 0; i < 512; i += 32)
                s = fmaf(hid[i + lane], w2[h * 512 + i + lane], s);
#pragma unroll
            for (int msk = 16; msk >= 1; msk >>= 1)
                s += __shfl_xor_sync(0xffffffffu, s, msk);
            if (lane == 0)
                tt[h * TBL + r] = s + b2[h];
        }
        __syncthreads();
    }
}

// ---------------------------------------------------------------------------
// Kernel 1/3: 3xBF16 split NT-GEMM (mma.sync). 128x128 tile, k-step 32.
// MODE 0: C fp32 = A B^T + bias.
// MODE 1: fused qkv norm/split epilogue + trailing rb blocks (tail fill).
// ---------------------------------------------------------------------------
#define GBUF 40960
#define GROW 40
#define RB_YBASE 64

template<int MODE>
__global__ __launch_bounds__(256, 2)
void gemm_bs(const bf16* __restrict__ Ahi, const bf16* __restrict__ Alo,
             const bf16* __restrict__ Bhi, const bf16* __restrict__ Blo,
             const float* __restrict__ bias, float* __restrict__ C,
             int M, int N, int K,
             const float* __restrict__ temp, const float* __restrict__ qe,
             const float* __restrict__ sls,
             bf16* __restrict__ Qhi, bf16* __restrict__ Qlo,
             bf16* __restrict__ Khi, bf16* __restrict__ Klo,
             bf16* __restrict__ Vhi, bf16* __restrict__ Vlo,
             const int* __restrict__ idx, const float* __restrict__ tt,
             bf16* __restrict__ rbout)
{
    extern __shared__ __align__(16) char smraw[];
    const uint32_t smb = smem_u32(smraw);
    const int tid = threadIdx.x;

    if (MODE == 1 && blockIdx.y >= RB_YBASE) {
        // ---------------- rb materialization path ----------------
        const int q = (blockIdx.y - RB_YBASE) * 12 + blockIdx.x;
        if (q >= NTOK) return;
        int* idxbuf = (int*)smraw;
        ((int4*)idxbuf)[tid] = ((const int4*)(idx + q * NTOK))[tid];
        __syncthreads();
        const int kp = tid * 4;
        const int blk = kp & ~63;
        const int j = kp & 63;
        const int tig = j >> 4;
        const int nt0 = (j & 15) >> 1;
        const int2 i0 = *(const int2*)&idxbuf[blk + nt0 * 8 + 2 * tig];
        const int2 i1 = *(const int2*)&idxbuf[blk + (nt0 + 1) * 8 + 2 * tig];
#pragma unroll 4
        for (int h = 0; h < HEADS; h++) {
            const float* tth = tt + h * TBL;
            ((uint2*)rbout)[(((size_t)h * NTOK + q) * NTOK + kp) >> 2] =
                make_uint2(packbf(tth[i0.x] * LOG2E, tth[i0.y] * LOG2E),
                           packbf(tth[i1.x] * LOG2E, tth[i1.y] * LOG2E));
        }
        return;
    }

    // ---------------- gemm path ----------------
    const int w = tid >> 5, lane = tid & 31;
    const int gid = lane >> 2, tig = lane & 3;
    const int wm = w >> 2, wn = w & 3;
    const int row0 = blockIdx.y * 128, col0 = blockIdx.x * 128;
    const int NS = K / 32;

    const int rowA = (lane & 7) | (lane & 8);
    const uint32_t aoff = (uint32_t)(rowA * GROW + ((lane & 16) >> 1)) * 2;
    const int rowB = (lane & 7) | ((lane & 16) >> 1);
    const uint32_t boff = (uint32_t)(rowB * GROW + (lane & 8)) * 2;

    float acc[4][4][4];
#pragma unroll
    for (int i = 0; i < 4; i++)
#pragma unroll
        for (int j = 0; j < 4; j++)
#pragma unroll
            for (int q = 0; q < 4; q++) acc[i][j][q] = 0.0f;

#define GEMM_LOAD(s, buf)                                                          \
    {                                                                              \
        const int k0_ = (s) * 32;                                                  \
        _Pragma("unroll")                                                          \
        for (int i_ = 0; i_ < 2; i_++) {                                           \
            const int slot_ = tid + i_ * 256;                                      \
            const int r_ = slot_ >> 2, q_ = slot_ & 3;                             \
            const uint32_t d_ = smb + (buf) * GBUF + (uint32_t)(r_ * 80 + q_ * 16);\
            const size_t ga_ = (size_t)(row0 + r_) * K + k0_ + q_ * 8;             \
            const size_t gb_ = (size_t)(col0 + r_) * K + k0_ + q_ * 8;             \
            cp16(d_,         Ahi + ga_);                                           \
            cp16(d_ + 10240, Alo + ga_);                                           \
            cp16(d_ + 20480, Bhi + gb_);                                           \
            cp16(d_ + 30720, Blo + gb_);                                           \
        }                                                                          \
        CP_COMMIT();                                                               \
    }

    GEMM_LOAD(0, 0);
    GEMM_LOAD(1, 1);

    for (int s = 0; s < NS; s++) {
        if (s < NS - 1) { CP_WAIT1(); } else { CP_WAIT0(); }
        __syncthreads();
        const uint32_t base = smb + (s & 1) * GBUF;
#pragma unroll
        for (int kt = 0; kt < 2; kt++) {
            unsigned bh[4][2], bl[4][2];
#pragma unroll
            for (int ntp = 0; ntp < 2; ntp++) {
                const uint32_t ba = base + 20480 + boff
                                  + (uint32_t)((wn * 32 + ntp * 16) * 80 + kt * 32);
                ldsm_x4(bh[2*ntp][0], bh[2*ntp][1], bh[2*ntp+1][0], bh[2*ntp+1][1], ba);
                ldsm_x4(bl[2*ntp][0], bl[2*ntp][1], bl[2*ntp+1][0], bl[2*ntp+1][1], ba + 10240);
            }
#pragma unroll
            for (int mt = 0; mt < 4; mt++) {
                const uint32_t aa = base + aoff
                                  + (uint32_t)((wm * 64 + mt * 16) * 80 + kt * 32);
                unsigned ah[4], al[4];
                ldsm_x4(ah[0], ah[1], ah[2], ah[3], aa);
                ldsm_x4(al[0], al[1], al[2], al[3], aa + 10240);
#pragma unroll
                for (int nt = 0; nt < 4; nt++) {
                    mma16(acc[mt][nt], ah, bh[nt][0], bh[nt][1]);
                    mma16(acc[mt][nt], al, bh[nt][0], bh[nt][1]);
                    mma16(acc[mt][nt], ah, bl[nt][0], bl[nt][1]);
                }
            }
        }
        __syncthreads();
        if (s + 2 < NS) GEMM_LOAD(s + 2, s & 1);
    }

    if (MODE == 0) {
#pragma unroll
        for (int mt = 0; mt < 4; mt++) {
            const int ra = row0 + wm * 64 + mt * 16 + gid;
#pragma unroll
            for (int nt = 0; nt < 4; nt++) {
                const int c = col0 + wn * 32 + nt * 8 + 2 * tig;
                const float bb0 = bias[c], bb1 = bias[c + 1];
                *(float2*)(C + (size_t)ra * N + c) =
                    make_float2(acc[mt][nt][0] + bb0, acc[mt][nt][1] + bb1);
                *(float2*)(C + (size_t)(ra + 8) * N + c) =
                    make_float2(acc[mt][nt][2] + bb0, acc[mt][nt][3] + bb1);
            }
        }
    } else {
        // fused qkv epilogue: warp owns 32 cols = one head slice
        const int cb = col0 + wn * 32;
        const int region = cb >> 9;                // 0:q 1:k 2:v
        const int h = (cb >> 5) & 15;
        float qscale = 0.0f;
        if (region == 0)
            qscale = log1pf(expf(temp[h])) * sls[0] * LOG2E;
        float bb[4][2];
        float qev[4][2];
#pragma unroll
        for (int nt = 0; nt < 4; nt++) {
            const int c = cb + nt * 8 + 2 * tig;
            bb[nt][0] = bias[c]; bb[nt][1] = bias[c + 1];
            if (region == 0) {
                qev[nt][0] = qe[h * HD + (c & 31)];
                qev[nt][1] = qe[h * HD + ((c + 1) & 31)];
            }
        }
        bf16* dsthi = (region == 0) ? Qhi : (region == 1) ? Khi : Vhi;
        bf16* dstlo = (region == 0) ? Qlo : (region == 1) ? Klo : Vlo;

#pragma unroll
        for (int mt = 0; mt < 4; mt++) {
#pragma unroll
            for (int half = 0; half < 2; half++) {
                const int r = row0 + wm * 64 + mt * 16 + gid + half * 8;
                const int b = r >> 10, n = r & 1023;
                float v[4][2];
                float s2 = 0.0f;
#pragma unroll
                for (int nt = 0; nt < 4; nt++) {
                    v[nt][0] = acc[mt][nt][2 * half + 0] + bb[nt][0];
                    v[nt][1] = acc[mt][nt][2 * half + 1] + bb[nt][1];
                    s2 = fmaf(v[nt][0], v[nt][0], fmaf(v[nt][1], v[nt][1], s2));
                }
                if (region < 2) {
                    s2 += __shfl_xor_sync(0xffffffffu, s2, 1);
                    s2 += __shfl_xor_sync(0xffffffffu, s2, 2);
                    const float inv = 1.0f / fmaxf(sqrtf(s2), 1e-12f);
#pragma unroll
                    for (int nt = 0; nt < 4; nt++) {
                        if (region == 0) {
                            v[nt][0] = (v[nt][0] * inv + qev[nt][0]) * qscale;
                            v[nt][1] = (v[nt][1] * inv + qev[nt][1]) * qscale;
                        } else {
                            v[nt][0] *= inv;
                            v[nt][1] *= inv;
                        }
                    }
                }
                const size_t obase = ((((size_t)b * HEADS + h) << 10) + n) * HD;
#pragma unroll
                for (int nt = 0; nt < 4; nt++) {
                    const int d = nt * 8 + 2 * tig;
                    bf16 h0, l0, h1, l1;
                    splitf(v[nt][0], h0, l0);
                    splitf(v[nt][1], h1, l1);
                    ((unsigned*)dsthi)[(obase + d) >> 1] =
                        packbf(__bfloat162float(h0), __bfloat162float(h1));
                    ((unsigned*)dstlo)[(obase + d) >> 1] =
                        packbf(__bfloat162float(l0), __bfloat162float(l1));
                }
            }
        }
    }
}

// ---------------------------------------------------------------------------
// Kernel 2: bf16-split flash attention (round-8 exact: 2-stage ring, bias-
// initialized S accumulators, register-direct P, V ldsm first).
// ---------------------------------------------------------------------------
#define KROW 40
#define KPS  (64 * KROW * 2)
#define STG  (4 * KPS)
#define ATTN_SMEM (2 * STG)

__global__ __launch_bounds__(256, 2)
void attn_mma(const bf16* __restrict__ Qhi_, const bf16* __restrict__ Qlo_,
              const bf16* __restrict__ Khi_, const bf16* __restrict__ Klo_,
              const bf16* __restrict__ Vhi_, const bf16* __restrict__ Vlo_,
              const bf16* __restrict__ rb, bf16* __restrict__ outhi,
              bf16* __restrict__ outlo)
{
    extern __shared__ __align__(16) char smraw[];
    const uint32_t smb = smem_u32(smraw);

    const int tid = threadIdx.x;
    const int w = tid >> 5, lane = tid & 31;
    const int gid = lane >> 2, tig = lane & 3;
    const int b = blockIdx.x, h = blockIdx.y, q0 = blockIdx.z * 128;
    const size_t bh = ((size_t)b * HEADS + h) * NTOK * HD;
    const bf16* Khg = Khi_ + bh;
    const bf16* Klg = Klo_ + bh;
    const bf16* Vhg = Vhi_ + bh;
    const bf16* Vlg = Vlo_ + bh;
    const bf16* rbh = rb + (size_t)h * NTOK * NTOK;
    const int r0 = q0 + w * 16 + gid;
    const int r1 = r0 + 8;

    const uint32_t koff = (uint32_t)((((lane & 7) | ((lane & 16) >> 1)) * KROW + (lane & 8)) * 2);
    const uint32_t voff = (uint32_t)((((lane & 7) | (lane & 8)) * KROW + ((lane & 16) >> 1)) * 2);

    unsigned qh[2][4], ql[2][4];
#pragma unroll
    for (int kt = 0; kt < 2; kt++) {
        const int d0 = kt * 16 + 2 * tig;
        qh[kt][0] = *(const unsigned*)(Qhi_ + bh + (size_t)r0 * HD + d0);
        qh[kt][1] = *(const unsigned*)(Qhi_ + bh + (size_t)r1 * HD + d0);
        qh[kt][2] = *(const unsigned*)(Qhi_ + bh + (size_t)r0 * HD + d0 + 8);
        qh[kt][3] = *(const unsigned*)(Qhi_ + bh + (size_t)r1 * HD + d0 + 8);
        ql[kt][0] = *(const unsigned*)(Qlo_ + bh + (size_t)r0 * HD + d0);
        ql[kt][1] = *(const unsigned*)(Qlo_ + bh + (size_t)r1 * HD + d0);
        ql[kt][2] = *(const unsigned*)(Qlo_ + bh + (size_t)r0 * HD + d0 + 8);
        ql[kt][3] = *(const unsigned*)(Qlo_ + bh + (size_t)r1 * HD + d0 + 8);
    }

    float o[4][4];
#pragma unroll
    for (int i = 0; i < 4; i++)
#pragma unroll
        for (int j = 0; j < 4; j++) o[i][j] = 0.0f;
    float l0 = 0.0f, l1 = 0.0f;

#define ATTN_LOAD(t, buf)                                                      \
    {                                                                          \
        const int r_ = tid >> 2, q_ = tid & 3;                                 \
        const uint32_t d_ = smb + (buf) * STG + (uint32_t)(r_ * 80 + q_ * 16); \
        const size_t g_ = (size_t)((t) * 64 + r_) * HD + q_ * 8;               \
        cp16(d_,           Khg + g_);                                          \
        cp16(d_ + KPS,     Klg + g_);                                          \
        cp16(d_ + 2 * KPS, Vhg + g_);                                          \
        cp16(d_ + 3 * KPS, Vlg + g_);                                          \
        CP_COMMIT();                                                           \
    }

    ATTN_LOAD(0, 0);

    for (int t = 0; t < 16; t++) {
        if (t < 15) ATTN_LOAD(t + 1, (t + 1) & 1);
        const int key0 = t * 64;

        // gathered bias (fragment-major): 4 x 16B loads cover the whole tile
        float s[8][4];
        {
            const bf16* rp0 = rbh + ((size_t)r0 << 10) + key0 + tig * 16;
            const bf16* rp1 = rbh + ((size_t)r1 << 10) + key0 + tig * 16;
            const uint4 Ua = *(const uint4*)rp0;
            const uint4 Ub = *(const uint4*)(rp0 + 8);
            const uint4 Uc = *(const uint4*)rp1;
            const uint4 Ud = *(const uint4*)(rp1 + 8);
            const unsigned pr0[8] = {Ua.x, Ua.y, Ua.z, Ua.w, Ub.x, Ub.y, Ub.z, Ub.w};
            const unsigned pr1[8] = {Uc.x, Uc.y, Uc.z, Uc.w, Ud.x, Ud.y, Ud.z, Ud.w};
#pragma unroll
            for (int nt = 0; nt < 8; nt++) {
                const float2 f0 = __bfloat1622float2(*(const __nv_bfloat162*)&pr0[nt]);
                const float2 f1 = __bfloat1622float2(*(const __nv_bfloat162*)&pr1[nt]);
                s[nt][0] = f0.x; s[nt][1] = f0.y; s[nt][2] = f1.x; s[nt][3] = f1.y;
            }
        }

        if (t < 15) { CP_WAIT1(); } else { CP_WAIT0(); }
        __syncthreads();
        const uint32_t base = smb + (t & 1) * STG;

        // ---- S += Q K^T (3xBF16)
#pragma unroll
        for (int kt = 0; kt < 2; kt++) {
#pragma unroll
            for (int ntp = 0; ntp < 4; ntp++) {
                const uint32_t ka = base + koff + (uint32_t)(ntp * 1280 + kt * 32);
                unsigned kh0, kh1, kh2, kh3, kl0, kl1, kl2, kl3;
                ldsm_x4(kh0, kh1, kh2, kh3, ka);
                ldsm_x4(kl0, kl1, kl2, kl3, ka + KPS);
                mma16(s[2*ntp],   qh[kt], kh0, kh1);
                mma16(s[2*ntp],   ql[kt], kh0, kh1);
                mma16(s[2*ntp],   qh[kt], kl0, kl1);
                mma16(s[2*ntp+1], qh[kt], kh2, kh3);
                mma16(s[2*ntp+1], ql[kt], kh2, kh3);
                mma16(s[2*ntp+1], qh[kt], kl2, kl3);
            }
        }

        // ---- fixed-offset softmax
#pragma unroll
        for (int nt = 0; nt < 8; nt++) {
            s[nt][0] = ex2(s[nt][0] - SMSHIFT);
            s[nt][1] = ex2(s[nt][1] - SMSHIFT);
            s[nt][2] = ex2(s[nt][2] - SMSHIFT);
            s[nt][3] = ex2(s[nt][3] - SMSHIFT);
            l0 += s[nt][0] + s[nt][1];
            l1 += s[nt][2] + s[nt][3];
        }

        // ---- O += P V: V ldsm issued FIRST, then register-direct P packs
#pragma unroll
        for (int kt = 0; kt < 4; kt++) {
            unsigned vh[8], vl[8];
#pragma unroll
            for (int ntp = 0; ntp < 2; ntp++) {
                const uint32_t va = base + 2 * KPS + voff + (uint32_t)(kt * 1280 + ntp * 32);
                ldsm_x4t(vh[4*ntp], vh[4*ntp+1], vh[4*ntp+2], vh[4*ntp+3], va);
                ldsm_x4t(vl[4*ntp], vl[4*ntp+1], vl[4*ntp+2], vl[4*ntp+3], va + KPS);
            }
            unsigned ph[4], pl[4];
#pragma unroll
            for (int half = 0; half < 2; half++) {
                const int nt = 2 * kt + half;
                const unsigned h01 = packbf(s[nt][0], s[nt][1]);
                const unsigned h23 = packbf(s[nt][2], s[nt][3]);
                const float2 f01 = __bfloat1622float2(*(const __nv_bfloat162*)&h01);
                const float2 f23 = __bfloat1622float2(*(const __nv_bfloat162*)&h23);
                ph[2 * half + 0] = h01;
                ph[2 * half + 1] = h23;
                pl[2 * half + 0] = packbf(s[nt][0] - f01.x, s[nt][1] - f01.y);
                pl[2 * half + 1] = packbf(s[nt][2] - f23.x, s[nt][3] - f23.y);
            }
#pragma unroll
            for (int ntp = 0; ntp < 2; ntp++) {
                mma16(o[2*ntp],   ph, vh[4*ntp+0], vh[4*ntp+1]);
                mma16(o[2*ntp],   pl, vh[4*ntp+0], vh[4*ntp+1]);
                mma16(o[2*ntp],   ph, vl[4*ntp+0], vl[4*ntp+1]);
                mma16(o[2*ntp+1], ph, vh[4*ntp+2], vh[4*ntp+3]);
                mma16(o[2*ntp+1], pl, vh[4*ntp+2], vh[4*ntp+3]);
                mma16(o[2*ntp+1], ph, vl[4*ntp+2], vl[4*ntp+3]);
            }
        }
        __syncthreads();
    }

    l0 += __shfl_xor_sync(0xffffffffu, l0, 1);
    l0 += __shfl_xor_sync(0xffffffffu, l0, 2);
    l1 += __shfl_xor_sync(0xffffffffu, l1, 1);
    l1 += __shfl_xor_sync(0xffffffffu, l1, 2);

    const float inv0 = 1.0f / l0, inv1 = 1.0f / l1;
#pragma unroll
    for (int dnt = 0; dnt < 4; dnt++) {
        const int c = h * HD + dnt * 8 + 2 * tig;
        {
            const float v0 = o[dnt][0] * inv0, v1 = o[dnt][1] * inv0;
            const float h0 = __bfloat162float(__float2bfloat16_rn(v0));
            const float h1 = __bfloat162float(__float2bfloat16_rn(v1));
            const size_t u = ((size_t)(((size_t)b << 10) + r0) * DIM + c) >> 1;
            ((unsigned*)outhi)[u] = packbf(v0, v1);
            ((unsigned*)outlo)[u] = packbf(v0 - h0, v1 - h1);
        }
        {
            const float v0 = o[dnt][2] * inv1, v1 = o[dnt][3] * inv1;
            const float h0 = __bfloat162float(__float2bfloat16_rn(v0));
            const float h1 = __bfloat162float(__float2bfloat16_rn(v1));
            const size_t u = ((size_t)(((size_t)b << 10) + r1) * DIM + c) >> 1;
            ((unsigned*)outhi)[u] = packbf(v0, v1);
            ((unsigned*)outlo)[u] = packbf(v0 - h0, v1 - h1);
        }
    }
}

// ---------------------------------------------------------------------------
extern "C" void kernel_launch(void* const* d_in, const int* in_sizes, int n_in,
                              void* d_out, int out_size)
{
    (void)in_sizes; (void)n_in; (void)out_size;
    const float* x      = (const float*)d_in[0];
    const float* qkv_w  = (const float*)d_in[1];
    const float* qkv_b  = (const float*)d_in[2];
    const float* proj_w = (const float*)d_in[3];
    const float* proj_b = (const float*)d_in[4];
    const float* temp   = (const float*)d_in[5];
    const float* qe     = (const float*)d_in[6];
    const float* c1w    = (const float*)d_in[7];
    const float* c1b    = (const float*)d_in[8];
    const float* c2w    = (const float*)d_in[9];
    const float* c2b    = (const float*)d_in[10];
    const float* rct    = (const float*)d_in[11];
    const int*   rpi    = (const int*)d_in[12];
    const float* sls    = (const float*)d_in[13];
    float* out = (float*)d_out;

    float *tt_s;
    bf16 *xhi, *xlo, *wqhi, *wqlo, *wphi, *wplo;
    bf16 *Qhi, *Qlo, *Khi, *Klo, *Vhi, *Vlo, *ahi, *alo, *rb_s;
    cudaGetSymbolAddress((void**)&tt_s,  g_tt);
    cudaGetSymbolAddress((void**)&xhi,  g_xhi);  cudaGetSymbolAddress((void**)&xlo,  g_xlo);
    cudaGetSymbolAddress((void**)&wqhi, g_wqhi); cudaGetSymbolAddress((void**)&wqlo, g_wqlo);
    cudaGetSymbolAddress((void**)&wphi, g_wphi); cudaGetSymbolAddress((void**)&wplo, g_wplo);
    cudaGetSymbolAddress((void**)&Qhi,  g_Qhi);  cudaGetSymbolAddress((void**)&Qlo,  g_Qlo);
    cudaGetSymbolAddress((void**)&Khi,  g_Khi);  cudaGetSymbolAddress((void**)&Klo,  g_Klo);
    cudaGetSymbolAddress((void**)&Vhi,  g_Vhi);  cudaGetSymbolAddress((void**)&Vlo,  g_Vlo);
    cudaGetSymbolAddress((void**)&ahi,  g_ahi);  cudaGetSymbolAddress((void**)&alo,  g_alo);
    cudaGetSymbolAddress((void**)&rb_s, g_rb);

    cudaFuncSetAttribute(attn_mma, cudaFuncAttributeMaxDynamicSharedMemorySize, ATTN_SMEM);
    cudaFuncSetAttribute(gemm_bs<0>, cudaFuncAttributeMaxDynamicSharedMemorySize, 2 * GBUF);
    cudaFuncSetAttribute(gemm_bs<1>, cudaFuncAttributeMaxDynamicSharedMemorySize, 2 * GBUF);

    // 0. fused prologue: splits + CPB MLP (8 rows/block)
    prologue_kernel<<<SPLITBLK + CPBBLK, 256>>>(
        x, qkv_w, proj_w, xhi, xlo, wqhi, wqlo, wphi, wplo,
        rct, c1w, c1b, c2w, c2b, tt_s);

    // 1. qkv projection (fused norm/split epilogue) + trailing rb blocks
    gemm_bs<1><<<dim3(12, RB_YBASE + 86), 256, 2 * GBUF>>>(
        xhi, xlo, wqhi, wqlo, qkv_b, nullptr, B_ * NTOK, 3 * DIM, DIM,
        temp, qe, sls, Qhi, Qlo, Khi, Klo, Vhi, Vlo,
        rpi, tt_s, rb_s);

    // 2. fused attention (batch fastest for rb L2 reuse)
    attn_mma<<<dim3(B_, HEADS, NTOK / 128), 256, ATTN_SMEM>>>(
        Qhi, Qlo, Khi, Klo, Vhi, Vlo, rb_s, ahi, alo);

    // 3. output projection (128x128 tiles, known-best config)
    gemm_bs<0><<<dim3(4, 64), 256, 2 * GBUF>>>(
        ahi, alo, wphi, wplo, proj_b, out, B_ * NTOK, DIM, DIM,
        nullptr, nullptr, nullptr,
        nullptr, nullptr, nullptr, nullptr, nullptr, nullptr,
        nullptr, nullptr, nullptr);
}

// round 15
// speedup vs baseline: 1.1306x; 1.0060x over previous
#include <cuda_runtime.h>
#include <cuda_bf16.h>
#include <cstdint>
#include <math.h>
#include <math_constants.h>

#define B_     8
#define NTOK   1024
#define DIM    512
#define HEADS  16
#define HD     32
#define TBL    3969
#define LOG2E  1.4426950408889634f
#define SMSHIFT 48.0f

typedef __nv_bfloat16 bf16;

// ---------------- scratch (device globals; no dynamic allocation) ----------
__device__ bf16  g_xhi[B_ * NTOK * DIM],        g_xlo[B_ * NTOK * DIM];
__device__ bf16  g_wqhi[3 * DIM * DIM],         g_wqlo[3 * DIM * DIM];
__device__ bf16  g_wphi[DIM * DIM],             g_wplo[DIM * DIM];
__device__ bf16  g_Qhi[B_ * HEADS * NTOK * HD], g_Qlo[B_ * HEADS * NTOK * HD];
__device__ bf16  g_Khi[B_ * HEADS * NTOK * HD], g_Klo[B_ * HEADS * NTOK * HD];
__device__ bf16  g_Vhi[B_ * HEADS * NTOK * HD], g_Vlo[B_ * HEADS * NTOK * HD];
__device__ bf16  g_ahi[B_ * NTOK * DIM],        g_alo[B_ * NTOK * DIM];
__device__ bf16  g_rb [HEADS * NTOK * NTOK];
__device__ float g_tt [HEADS * TBL];

// ---------------------------------------------------------------------------
// helpers
// ---------------------------------------------------------------------------
__device__ __forceinline__ void mma16(float* d, const unsigned* a, unsigned b0, unsigned b1) {
    asm volatile("mma.sync.aligned.m16n8k16.row.col.f32.bf16.bf16.f32 "
                 "{%0,%1,%2,%3}, {%4,%5,%6,%7}, {%8,%9}, {%0,%1,%2,%3};"
                 : "+f"(d[0]), "+f"(d[1]), "+f"(d[2]), "+f"(d[3])
                 : "r"(a[0]), "r"(a[1]), "r"(a[2]), "r"(a[3]), "r"(b0), "r"(b1));
}
__device__ __forceinline__ void ldsm_x4(unsigned& r0, unsigned& r1, unsigned& r2,
                                        unsigned& r3, unsigned addr) {
    asm volatile("ldmatrix.sync.aligned.m8n8.x4.shared.b16 {%0,%1,%2,%3}, [%4];"
                 : "=r"(r0), "=r"(r1), "=r"(r2), "=r"(r3) : "r"(addr));
}
__device__ __forceinline__ void ldsm_x4t(unsigned& r0, unsigned& r1, unsigned& r2,
                                         unsigned& r3, unsigned addr) {
    asm volatile("ldmatrix.sync.aligned.m8n8.x4.trans.shared.b16 {%0,%1,%2,%3}, [%4];"
                 : "=r"(r0), "=r"(r1), "=r"(r2), "=r"(r3) : "r"(addr));
}
__device__ __forceinline__ void cp16(uint32_t dst, const void* src) {
    asm volatile("cp.async.cg.shared.global [%0], [%1], 16;" :: "r"(dst), "l"(src));
}
#define CP_COMMIT() asm volatile("cp.async.commit_group;" ::: "memory")
#define CP_WAIT1()  asm volatile("cp.async.wait_group 1;" ::: "memory")
#define CP_WAIT0()  asm volatile("cp.async.wait_group 0;" ::: "memory")

__device__ __forceinline__ unsigned packbf(float a, float b) {
    __nv_bfloat162 h = __floats2bfloat162_rn(a, b);
    return *(unsigned*)&h;
}
__device__ __forceinline__ void splitf(float x, bf16& hi, bf16& lo) {
    hi = __float2bfloat16_rn(x);
    lo = __float2bfloat16_rn(x - __bfloat162float(hi));
}
__device__ __forceinline__ float ex2(float x) {
    float r;
    asm("ex2.approx.ftz.f32 %0, %1;" : "=f"(r) : "f"(x));
    return r;
}
__device__ __forceinline__ uint32_t smem_u32(const void* p) {
    return (uint32_t)__cvta_generic_to_shared(p);
}

// ---------------------------------------------------------------------------
// Kernel 0: fused prologue — splits + CPB MLP (8 rows/block).
// ---------------------------------------------------------------------------
#define XELEM  (B_ * NTOK * DIM)
#define WQELEM (3 * DIM * DIM)
#define WPELEM (DIM * DIM)
#define XBLK   (XELEM / 1024)
#define WQBLK  (WQELEM / 1024)
#define WPBLK  (WPELEM / 1024)
#define SPLITBLK (XBLK + WQBLK + WPBLK)
#define CPB_RPB 8
#define CPBBLK ((TBL + CPB_RPB - 1) / CPB_RPB)

__global__ __launch_bounds__(256)
void prologue_kernel(const float* __restrict__ x, const float* __restrict__ qkv_w,
                     const float* __restrict__ proj_w,
                     bf16* __restrict__ xhi, bf16* __restrict__ xlo,
                     bf16* __restrict__ wqhi, bf16* __restrict__ wqlo,
                     bf16* __restrict__ wphi, bf16* __restrict__ wplo,
                     const float* __restrict__ tbl, const float* __restrict__ w1,
                     const float* __restrict__ b1, const float* __restrict__ w2,
                     const float* __restrict__ b2, float* __restrict__ tt)
{
    const int bid = blockIdx.x;
    const int tid = threadIdx.x;
    if (bid < SPLITBLK) {
        const float* in;
        bf16 *hi, *lo;
        int base;
        if (bid < XBLK)              { in = x;      hi = xhi;  lo = xlo;  base = bid; }
        else if (bid < XBLK + WQBLK) { in = qkv_w;  hi = wqhi; lo = wqlo; base = bid - XBLK; }
        else                         { in = proj_w; hi = wphi; lo = wplo; base = bid - XBLK - WQBLK; }
        const int i = base * 1024 + tid * 4;
        const float4 v = *(const float4*)(in + i);
        bf16 h0, h1, h2, h3, l0, l1, l2, l3;
        splitf(v.x, h0, l0); splitf(v.y, h1, l1);
        splitf(v.z, h2, l2); splitf(v.w, h3, l3);
        ((uint2*)hi)[i >> 2] = make_uint2(packbf(__bfloat162float(h0), __bfloat162float(h1)),
                                          packbf(__bfloat162float(h2), __bfloat162float(h3)));
        ((uint2*)lo)[i >> 2] = make_uint2(packbf(__bfloat162float(l0), __bfloat162float(l1)),
                                          packbf(__bfloat162float(l2), __bfloat162float(l3)));
        return;
    }
    const int r0b = (bid - SPLITBLK) * CPB_RPB;
    __shared__ float hid[512];
    const int w = tid >> 5, lane = tid & 31;
#pragma unroll
    for (int rr = 0; rr < CPB_RPB; rr++) {
        const int r = r0b + rr;
        if (r >= TBL) break;
        const float c0 = tbl[r * 2 + 0];
        const float c1 = tbl[r * 2 + 1];
        hid[tid]       = fmaxf(fmaf(c0, w1[tid * 2 + 0],
                               fmaf(c1, w1[tid * 2 + 1], b1[tid])), 0.0f);
        hid[tid + 256] = fmaxf(fmaf(c0, w1[(tid + 256) * 2 + 0],
                               fmaf(c1, w1[(tid + 256) * 2 + 1], b1[tid + 256])), 0.0f);
        __syncthreads();
#pragma unroll
        for (int hh = 0; hh < 2; hh++) {
            const int h = w * 2 + hh;
            float s = 0.0f;
#pragma unroll
            for (int i = 0; i < 512; i += 32)
                s = fmaf(hid[i + lane], w2[h * 512 + i + lane], s);
#pragma unroll
            for (int msk = 16; msk >= 1; msk >>= 1)
                s += __shfl_xor_sync(0xffffffffu, s, msk);
            if (lane == 0)
                tt[h * TBL + r] = s + b2[h];
        }
        __syncthreads();
    }
}

// ---------------------------------------------------------------------------
// Kernel: rb materialization (standalone; overlapped on side stream).
// One block per q row; idx row cached in smem; all 16 heads.
// ---------------------------------------------------------------------------
__global__ __launch_bounds__(256)
void rb_kernel(const int* __restrict__ idx, const float* __restrict__ tt,
               bf16* __restrict__ rbout)
{
    extern __shared__ __align__(16) char smraw[];
    const int q = blockIdx.x;
    const int tid = threadIdx.x;
    int* idxbuf = (int*)smraw;
    ((int4*)idxbuf)[tid] = ((const int4*)(idx + q * NTOK))[tid];
    __syncthreads();
    const int kp = tid * 4;
    const int blk = kp & ~63;
    const int j = kp & 63;
    const int tig = j >> 4;
    const int nt0 = (j & 15) >> 1;
    const int2 i0 = *(const int2*)&idxbuf[blk + nt0 * 8 + 2 * tig];
    const int2 i1 = *(const int2*)&idxbuf[blk + (nt0 + 1) * 8 + 2 * tig];
#pragma unroll 4
    for (int h = 0; h < HEADS; h++) {
        const float* tth = tt + h * TBL;
        ((uint2*)rbout)[(((size_t)h * NTOK + q) * NTOK + kp) >> 2] =
            make_uint2(packbf(tth[i0.x] * LOG2E, tth[i0.y] * LOG2E),
                       packbf(tth[i1.x] * LOG2E, tth[i1.y] * LOG2E));
    }
}

// ---------------------------------------------------------------------------
// Kernel: 3xBF16 split NT-GEMM (mma.sync). 128x128 tile, k-step 32.
// MODE 0: C fp32 = A B^T + bias.   MODE 1: fused qkv norm/split epilogue.
// yoff: row-block offset (batch-half pipelining).
// ---------------------------------------------------------------------------
#define GBUF 40960
#define GROW 40

template<int MODE>
__global__ __launch_bounds__(256, 2)
void gemm_bs(const bf16* __restrict__ Ahi, const bf16* __restrict__ Alo,
             const bf16* __restrict__ Bhi, const bf16* __restrict__ Blo,
             const float* __restrict__ bias, float* __restrict__ C,
             int M, int N, int K, int yoff,
             const float* __restrict__ temp, const float* __restrict__ qe,
             const float* __restrict__ sls,
             bf16* __restrict__ Qhi, bf16* __restrict__ Qlo,
             bf16* __restrict__ Khi, bf16* __restrict__ Klo,
             bf16* __restrict__ Vhi, bf16* __restrict__ Vlo)
{
    extern __shared__ __align__(16) char smraw[];
    const uint32_t smb = smem_u32(smraw);
    const int tid = threadIdx.x;
    const int w = tid >> 5, lane = tid & 31;
    const int gid = lane >> 2, tig = lane & 3;
    const int wm = w >> 2, wn = w & 3;
    const int row0 = (blockIdx.y + yoff) * 128, col0 = blockIdx.x * 128;
    const int NS = K / 32;

    const int rowA = (lane & 7) | (lane & 8);
    const uint32_t aoff = (uint32_t)(rowA * GROW + ((lane & 16) >> 1)) * 2;
    const int rowB = (lane & 7) | ((lane & 16) >> 1);
    const uint32_t boff = (uint32_t)(rowB * GROW + (lane & 8)) * 2;

    float acc[4][4][4];
#pragma unroll
    for (int i = 0; i < 4; i++)
#pragma unroll
        for (int j = 0; j < 4; j++)
#pragma unroll
            for (int q = 0; q < 4; q++) acc[i][j][q] = 0.0f;

#define GEMM_LOAD(s, buf)                                                          \
    {                                                                              \
        const int k0_ = (s) * 32;                                                  \
        _Pragma("unroll")                                                          \
        for (int i_ = 0; i_ < 2; i_++) {                                           \
            const int slot_ = tid + i_ * 256;                                      \
            const int r_ = slot_ >> 2, q_ = slot_ & 3;                             \
            const uint32_t d_ = smb + (buf) * GBUF + (uint32_t)(r_ * 80 + q_ * 16);\
            const size_t ga_ = (size_t)(row0 + r_) * K + k0_ + q_ * 8;             \
            const size_t gb_ = (size_t)(col0 + r_) * K + k0_ + q_ * 8;             \
            cp16(d_,         Ahi + ga_);                                           \
            cp16(d_ + 10240, Alo + ga_);                                           \
            cp16(d_ + 20480, Bhi + gb_);                                           \
            cp16(d_ + 30720, Blo + gb_);                                           \
        }                                                                          \
        CP_COMMIT();                                                               \
    }

    GEMM_LOAD(0, 0);
    GEMM_LOAD(1, 1);

    for (int s = 0; s < NS; s++) {
        if (s < NS - 1) { CP_WAIT1(); } else { CP_WAIT0(); }
        __syncthreads();
        const uint32_t base = smb + (s & 1) * GBUF;
#pragma unroll
        for (int kt = 0; kt < 2; kt++) {
            unsigned bh[4][2], bl[4][2];
#pragma unroll
            for (int ntp = 0; ntp < 2; ntp++) {
                const uint32_t ba = base + 20480 + boff
                                  + (uint32_t)((wn * 32 + ntp * 16) * 80 + kt * 32);
                ldsm_x4(bh[2*ntp][0], bh[2*ntp][1], bh[2*ntp+1][0], bh[2*ntp+1][1], ba);
                ldsm_x4(bl[2*ntp][0], bl[2*ntp][1], bl[2*ntp+1][0], bl[2*ntp+1][1], ba + 10240);
            }
#pragma unroll
            for (int mt = 0; mt < 4; mt++) {
                const uint32_t aa = base + aoff
                                  + (uint32_t)((wm * 64 + mt * 16) * 80 + kt * 32);
                unsigned ah[4], al[4];
                ldsm_x4(ah[0], ah[1], ah[2], ah[3], aa);
                ldsm_x4(al[0], al[1], al[2], al[3], aa + 10240);
#pragma unroll
                for (int nt = 0; nt < 4; nt++) {
                    mma16(acc[mt][nt], ah, bh[nt][0], bh[nt][1]);
                    mma16(acc[mt][nt], al, bh[nt][0], bh[nt][1]);
                    mma16(acc[mt][nt], ah, bl[nt][0], bl[nt][1]);
                }
            }
        }
        __syncthreads();
        if (s + 2 < NS) GEMM_LOAD(s + 2, s & 1);
    }

    if (MODE == 0) {
#pragma unroll
        for (int mt = 0; mt < 4; mt++) {
            const int ra = row0 + wm * 64 + mt * 16 + gid;
#pragma unroll
            for (int nt = 0; nt < 4; nt++) {
                const int c = col0 + wn * 32 + nt * 8 + 2 * tig;
                const float bb0 = bias[c], bb1 = bias[c + 1];
                *(float2*)(C + (size_t)ra * N + c) =
                    make_float2(acc[mt][nt][0] + bb0, acc[mt][nt][1] + bb1);
                *(float2*)(C + (size_t)(ra + 8) * N + c) =
                    make_float2(acc[mt][nt][2] + bb0, acc[mt][nt][3] + bb1);
            }
        }
    } else {
        const int cb = col0 + wn * 32;
        const int region = cb >> 9;
        const int h = (cb >> 5) & 15;
        float qscale = 0.0f;
        if (region == 0)
            qscale = log1pf(expf(temp[h])) * sls[0] * LOG2E;
        float bb[4][2];
        float qev[4][2];
#pragma unroll
        for (int nt = 0; nt < 4; nt++) {
            const int c = cb + nt * 8 + 2 * tig;
            bb[nt][0] = bias[c]; bb[nt][1] = bias[c + 1];
            if (region == 0) {
                qev[nt][0] = qe[h * HD + (c & 31)];
                qev[nt][1] = qe[h * HD + ((c + 1) & 31)];
            }
        }
        bf16* dsthi = (region == 0) ? Qhi : (region == 1) ? Khi : Vhi;
        bf16* dstlo = (region == 0) ? Qlo : (region == 1) ? Klo : Vlo;

#pragma unroll
        for (int mt = 0; mt < 4; mt++) {
#pragma unroll
            for (int half = 0; half < 2; half++) {
                const int r = row0 + wm * 64 + mt * 16 + gid + half * 8;
                const int b = r >> 10, n = r & 1023;
                float v[4][2];
                float s2 = 0.0f;
#pragma unroll
                for (int nt = 0; nt < 4; nt++) {
                    v[nt][0] = acc[mt][nt][2 * half + 0] + bb[nt][0];
                    v[nt][1] = acc[mt][nt][2 * half + 1] + bb[nt][1];
                    s2 = fmaf(v[nt][0], v[nt][0], fmaf(v[nt][1], v[nt][1], s2));
                }
                if (region < 2) {
                    s2 += __shfl_xor_sync(0xffffffffu, s2, 1);
                    s2 += __shfl_xor_sync(0xffffffffu, s2, 2);
                    const float inv = 1.0f / fmaxf(sqrtf(s2), 1e-12f);
#pragma unroll
                    for (int nt = 0; nt < 4; nt++) {
                        if (region == 0) {
                            v[nt][0] = (v[nt][0] * inv + qev[nt][0]) * qscale;
                            v[nt][1] = (v[nt][1] * inv + qev[nt][1]) * qscale;
                        } else {
                            v[nt][0] *= inv;
                            v[nt][1] *= inv;
                        }
                    }
                }
                const size_t obase = ((((size_t)b * HEADS + h) << 10) + n) * HD;
#pragma unroll
                for (int nt = 0; nt < 4; nt++) {
                    const int d = nt * 8 + 2 * tig;
                    bf16 h0, l0, h1, l1;
                    splitf(v[nt][0], h0, l0);
                    splitf(v[nt][1], h1, l1);
                    ((unsigned*)dsthi)[(obase + d) >> 1] =
                        packbf(__bfloat162float(h0), __bfloat162float(h1));
                    ((unsigned*)dstlo)[(obase + d) >> 1] =
                        packbf(__bfloat162float(l0), __bfloat162float(l1));
                }
            }
        }
    }
}

// ---------------------------------------------------------------------------
// Kernel: bf16-split flash attention (round-8 exact body; b0 = batch offset).
// ---------------------------------------------------------------------------
#define KROW 40
#define KPS  (64 * KROW * 2)
#define STG  (4 * KPS)
#define ATTN_SMEM (2 * STG)

__global__ __launch_bounds__(256, 2)
void attn_mma(const bf16* __restrict__ Qhi_, const bf16* __restrict__ Qlo_,
              const bf16* __restrict__ Khi_, const bf16* __restrict__ Klo_,
              const bf16* __restrict__ Vhi_, const bf16* __restrict__ Vlo_,
              const bf16* __restrict__ rb, bf16* __restrict__ outhi,
              bf16* __restrict__ outlo, int b0)
{
    extern __shared__ __align__(16) char smraw[];
    const uint32_t smb = smem_u32(smraw);

    const int tid = threadIdx.x;
    const int w = tid >> 5, lane = tid & 31;
    const int gid = lane >> 2, tig = lane & 3;
    const int b = blockIdx.x + b0, h = blockIdx.y, q0 = blockIdx.z * 128;
    const size_t bh = ((size_t)b * HEADS + h) * NTOK * HD;
    const bf16* Khg = Khi_ + bh;
    const bf16* Klg = Klo_ + bh;
    const bf16* Vhg = Vhi_ + bh;
    const bf16* Vlg = Vlo_ + bh;
    const bf16* rbh = rb + (size_t)h * NTOK * NTOK;
    const int r0 = q0 + w * 16 + gid;
    const int r1 = r0 + 8;

    const uint32_t koff = (uint32_t)((((lane & 7) | ((lane & 16) >> 1)) * KROW + (lane & 8)) * 2);
    const uint32_t voff = (uint32_t)((((lane & 7) | (lane & 8)) * KROW + ((lane & 16) >> 1)) * 2);

    unsigned qh[2][4], ql[2][4];
#pragma unroll
    for (int kt = 0; kt < 2; kt++) {
        const int d0 = kt * 16 + 2 * tig;
        qh[kt][0] = *(const unsigned*)(Qhi_ + bh + (size_t)r0 * HD + d0);
        qh[kt][1] = *(const unsigned*)(Qhi_ + bh + (size_t)r1 * HD + d0);
        qh[kt][2] = *(const unsigned*)(Qhi_ + bh + (size_t)r0 * HD + d0 + 8);
        qh[kt][3] = *(const unsigned*)(Qhi_ + bh + (size_t)r1 * HD + d0 + 8);
        ql[kt][0] = *(const unsigned*)(Qlo_ + bh + (size_t)r0 * HD + d0);
        ql[kt][1] = *(const unsigned*)(Qlo_ + bh + (size_t)r1 * HD + d0);
        ql[kt][2] = *(const unsigned*)(Qlo_ + bh + (size_t)r0 * HD + d0 + 8);
        ql[kt][3] = *(const unsigned*)(Qlo_ + bh + (size_t)r1 * HD + d0 + 8);
    }

    float o[4][4];
#pragma unroll
    for (int i = 0; i < 4; i++)
#pragma unroll
        for (int j = 0; j < 4; j++) o[i][j] = 0.0f;
    float l0 = 0.0f, l1 = 0.0f;

#define ATTN_LOAD(t, buf)                                                      \
    {                                                                          \
        const int r_ = tid >> 2, q_ = tid & 3;                                 \
        const uint32_t d_ = smb + (buf) * STG + (uint32_t)(r_ * 80 + q_ * 16); \
        const size_t g_ = (size_t)((t) * 64 + r_) * HD + q_ * 8;               \
        cp16(d_,           Khg + g_);                                          \
        cp16(d_ + KPS,     Klg + g_);                                          \
        cp16(d_ + 2 * KPS, Vhg + g_);                                          \
        cp16(d_ + 3 * KPS, Vlg + g_);                                          \
        CP_COMMIT();                                                           \
    }

    ATTN_LOAD(0, 0);

    for (int t = 0; t < 16; t++) {
        if (t < 15) ATTN_LOAD(t + 1, (t + 1) & 1);
        const int key0 = t * 64;

        float s[8][4];
        {
            const bf16* rp0 = rbh + ((size_t)r0 << 10) + key0 + tig * 16;
            const bf16* rp1 = rbh + ((size_t)r1 << 10) + key0 + tig * 16;
            const uint4 Ua = *(const uint4*)rp0;
            const uint4 Ub = *(const uint4*)(rp0 + 8);
            const uint4 Uc = *(const uint4*)rp1;
            const uint4 Ud = *(const uint4*)(rp1 + 8);
            const unsigned pr0[8] = {Ua.x, Ua.y, Ua.z, Ua.w, Ub.x, Ub.y, Ub.z, Ub.w};
            const unsigned pr1[8] = {Uc.x, Uc.y, Uc.z, Uc.w, Ud.x, Ud.y, Ud.z, Ud.w};
#pragma unroll
            for (int nt = 0; nt < 8; nt++) {
                const float2 f0 = __bfloat1622float2(*(const __nv_bfloat162*)&pr0[nt]);
                const float2 f1 = __bfloat1622float2(*(const __nv_bfloat162*)&pr1[nt]);
                s[nt][0] = f0.x; s[nt][1] = f0.y; s[nt][2] = f1.x; s[nt][3] = f1.y;
            }
        }

        if (t < 15) { CP_WAIT1(); } else { CP_WAIT0(); }
        __syncthreads();
        const uint32_t base = smb + (t & 1) * STG;

#pragma unroll
        for (int kt = 0; kt < 2; kt++) {
#pragma unroll
            for (int ntp = 0; ntp < 4; ntp++) {
                const uint32_t ka = base + koff + (uint32_t)(ntp * 1280 + kt * 32);
                unsigned kh0, kh1, kh2, kh3, kl0, kl1, kl2, kl3;
                ldsm_x4(kh0, kh1, kh2, kh3, ka);
                ldsm_x4(kl0, kl1, kl2, kl3, ka + KPS);
                mma16(s[2*ntp],   qh[kt], kh0, kh1);
                mma16(s[2*ntp],   ql[kt], kh0, kh1);
                mma16(s[2*ntp],   qh[kt], kl0, kl1);
                mma16(s[2*ntp+1], qh[kt], kh2, kh3);
                mma16(s[2*ntp+1], ql[kt], kh2, kh3);
                mma16(s[2*ntp+1], qh[kt], kl2, kl3);
            }
        }

#pragma unroll
        for (int nt = 0; nt < 8; nt++) {
            s[nt][0] = ex2(s[nt][0] - SMSHIFT);
            s[nt][1] = ex2(s[nt][1] - SMSHIFT);
            s[nt][2] = ex2(s[nt][2] - SMSHIFT);
            s[nt][3] = ex2(s[nt][3] - SMSHIFT);
            l0 += s[nt][0] + s[nt][1];
            l1 += s[nt][2] + s[nt][3];
        }

#pragma unroll
        for (int kt = 0; kt < 4; kt++) {
            unsigned vh[8], vl[8];
#pragma unroll
            for (int ntp = 0; ntp < 2; ntp++) {
                const uint32_t va = base + 2 * KPS + voff + (uint32_t)(kt * 1280 + ntp * 32);
                ldsm_x4t(vh[4*ntp], vh[4*ntp+1], vh[4*ntp+2], vh[4*ntp+3], va);
                ldsm_x4t(vl[4*ntp], vl[4*ntp+1], vl[4*ntp+2], vl[4*ntp+3], va + KPS);
            }
            unsigned ph[4], pl[4];
#pragma unroll
            for (int half = 0; half < 2; half++) {
                const int nt = 2 * kt + half;
                const unsigned h01 = packbf(s[nt][0], s[nt][1]);
                const unsigned h23 = packbf(s[nt][2], s[nt][3]);
                const float2 f01 = __bfloat1622float2(*(const __nv_bfloat162*)&h01);
                const float2 f23 = __bfloat1622float2(*(const __nv_bfloat162*)&h23);
                ph[2 * half + 0] = h01;
                ph[2 * half + 1] = h23;
                pl[2 * half + 0] = packbf(s[nt][0] - f01.x, s[nt][1] - f01.y);
                pl[2 * half + 1] = packbf(s[nt][2] - f23.x, s[nt][3] - f23.y);
            }
#pragma unroll
            for (int ntp = 0; ntp < 2; ntp++) {
                mma16(o[2*ntp],   ph, vh[4*ntp+0], vh[4*ntp+1]);
                mma16(o[2*ntp],   pl, vh[4*ntp+0], vh[4*ntp+1]);
                mma16(o[2*ntp],   ph, vl[4*ntp+0], vl[4*ntp+1]);
                mma16(o[2*ntp+1], ph, vh[4*ntp+2], vh[4*ntp+3]);
                mma16(o[2*ntp+1], pl, vh[4*ntp+2], vh[4*ntp+3]);
                mma16(o[2*ntp+1], ph, vl[4*ntp+2], vl[4*ntp+3]);
            }
        }
        __syncthreads();
    }

    l0 += __shfl_xor_sync(0xffffffffu, l0, 1);
    l0 += __shfl_xor_sync(0xffffffffu, l0, 2);
    l1 += __shfl_xor_sync(0xffffffffu, l1, 1);
    l1 += __shfl_xor_sync(0xffffffffu, l1, 2);

    const float inv0 = 1.0f / l0, inv1 = 1.0f / l1;
#pragma unroll
    for (int dnt = 0; dnt < 4; dnt++) {
        const int c = h * HD + dnt * 8 + 2 * tig;
        {
            const float v0 = o[dnt][0] * inv0, v1 = o[dnt][1] * inv0;
            const float h0 = __bfloat162float(__float2bfloat16_rn(v0));
            const float h1 = __bfloat162float(__float2bfloat16_rn(v1));
            const size_t u = ((size_t)(((size_t)b << 10) + r0) * DIM + c) >> 1;
            ((unsigned*)outhi)[u] = packbf(v0, v1);
            ((unsigned*)outlo)[u] = packbf(v0 - h0, v1 - h1);
        }
        {
            const float v0 = o[dnt][2] * inv1, v1 = o[dnt][3] * inv1;
            const float h0 = __bfloat162float(__float2bfloat16_rn(v0));
            const float h1 = __bfloat162float(__float2bfloat16_rn(v1));
            const size_t u = ((size_t)(((size_t)b << 10) + r1) * DIM + c) >> 1;
            ((unsigned*)outhi)[u] = packbf(v0, v1);
            ((unsigned*)outlo)[u] = packbf(v0 - h0, v1 - h1);
        }
    }
}

// ---------------------------------------------------------------------------
extern "C" void kernel_launch(void* const* d_in, const int* in_sizes, int n_in,
                              void* d_out, int out_size)
{
    (void)in_sizes; (void)n_in; (void)out_size;
    const float* x      = (const float*)d_in[0];
    const float* qkv_w  = (const float*)d_in[1];
    const float* qkv_b  = (const float*)d_in[2];
    const float* proj_w = (const float*)d_in[3];
    const float* proj_b = (const float*)d_in[4];
    const float* temp   = (const float*)d_in[5];
    const float* qe     = (const float*)d_in[6];
    const float* c1w    = (const float*)d_in[7];
    const float* c1b    = (const float*)d_in[8];
    const float* c2w    = (const float*)d_in[9];
    const float* c2b    = (const float*)d_in[10];
    const float* rct    = (const float*)d_in[11];
    const int*   rpi    = (const int*)d_in[12];
    const float* sls    = (const float*)d_in[13];
    float* out = (float*)d_out;

    float *tt_s;
    bf16 *xhi, *xlo, *wqhi, *wqlo, *wphi, *wplo;
    bf16 *Qhi, *Qlo, *Khi, *Klo, *Vhi, *Vlo, *ahi, *alo, *rb_s;
    cudaGetSymbolAddress((void**)&tt_s,  g_tt);
    cudaGetSymbolAddress((void**)&xhi,  g_xhi);  cudaGetSymbolAddress((void**)&xlo,  g_xlo);
    cudaGetSymbolAddress((void**)&wqhi, g_wqhi); cudaGetSymbolAddress((void**)&wqlo, g_wqlo);
    cudaGetSymbolAddress((void**)&wphi, g_wphi); cudaGetSymbolAddress((void**)&wplo, g_wplo);
    cudaGetSymbolAddress((void**)&Qhi,  g_Qhi);  cudaGetSymbolAddress((void**)&Qlo,  g_Qlo);
    cudaGetSymbolAddress((void**)&Khi,  g_Khi);  cudaGetSymbolAddress((void**)&Klo,  g_Klo);
    cudaGetSymbolAddress((void**)&Vhi,  g_Vhi);  cudaGetSymbolAddress((void**)&Vlo,  g_Vlo);
    cudaGetSymbolAddress((void**)&ahi,  g_ahi);  cudaGetSymbolAddress((void**)&alo,  g_alo);
    cudaGetSymbolAddress((void**)&rb_s, g_rb);

    cudaFuncSetAttribute(attn_mma, cudaFuncAttributeMaxDynamicSharedMemorySize, ATTN_SMEM);
    cudaFuncSetAttribute(gemm_bs<0>, cudaFuncAttributeMaxDynamicSharedMemorySize, 2 * GBUF);
    cudaFuncSetAttribute(gemm_bs<1>, cudaFuncAttributeMaxDynamicSharedMemorySize, 2 * GBUF);

    // fork stream + events (graph-capturable; not destroyed — handles are
    // host-side and kernel_launch is called a bounded number of times)
    cudaStream_t s1;
    cudaStreamCreateWithFlags(&s1, cudaStreamNonBlocking);
    cudaEvent_t eP, e1, eRB, f1;
    cudaEventCreateWithFlags(&eP,  cudaEventDisableTiming);
    cudaEventCreateWithFlags(&e1,  cudaEventDisableTiming);
    cudaEventCreateWithFlags(&eRB, cudaEventDisableTiming);
    cudaEventCreateWithFlags(&f1,  cudaEventDisableTiming);

    // ---- s0: prologue
    prologue_kernel<<<SPLITBLK + CPBBLK, 256>>>(
        x, qkv_w, proj_w, xhi, xlo, wqhi, wqlo, wphi, wplo,
        rct, c1w, c1b, c2w, c2b, tt_s);
    cudaEventRecord(eP, 0);

    // ---- s0: qkv half 1 (batches 0-3 = rows 0..4095)
    gemm_bs<1><<<dim3(12, 32), 256, 2 * GBUF>>>(
        xhi, xlo, wqhi, wqlo, qkv_b, nullptr, B_ * NTOK, 3 * DIM, DIM, 0,
        temp, qe, sls, Qhi, Qlo, Khi, Klo, Vhi, Vlo);
    cudaEventRecord(e1, 0);

    // ---- s1: rb (overlaps qkv half 1), then attn half 1, then proj half 1
    cudaStreamWaitEvent(s1, eP, 0);
    rb_kernel<<<NTOK, 256, 16384, s1>>>(rpi, tt_s, rb_s);
    cudaEventRecord(eRB, s1);
    cudaStreamWaitEvent(s1, e1, 0);
    attn_mma<<<dim3(4, HEADS, NTOK / 128), 256, ATTN_SMEM, s1>>>(
        Qhi, Qlo, Khi, Klo, Vhi, Vlo, rb_s, ahi, alo, 0);
    gemm_bs<0><<<dim3(4, 32), 256, 2 * GBUF, s1>>>(
        ahi, alo, wphi, wplo, proj_b, out, B_ * NTOK, DIM, DIM, 0,
        nullptr, nullptr, nullptr,
        nullptr, nullptr, nullptr, nullptr, nullptr, nullptr);
    cudaEventRecord(f1, s1);

    // ---- s0: qkv half 2 (batches 4-7), then attn half 2 (needs rb), proj half 2
    gemm_bs<1><<<dim3(12, 32), 256, 2 * GBUF>>>(
        xhi, xlo, wqhi, wqlo, qkv_b, nullptr, B_ * NTOK, 3 * DIM, DIM, 32,
        temp, qe, sls, Qhi, Qlo, Khi, Klo, Vhi, Vlo);
    cudaStreamWaitEvent(0, eRB, 0);
    attn_mma<<<dim3(4, HEADS, NTOK / 128), 256, ATTN_SMEM>>>(
        Qhi, Qlo, Khi, Klo, Vhi, Vlo, rb_s, ahi, alo, 4);
    gemm_bs<0><<<dim3(4, 32), 256, 2 * GBUF>>>(
        ahi, alo, wphi, wplo, proj_b, out, B_ * NTOK, DIM, DIM, 32,
        nullptr, nullptr, nullptr,
        nullptr, nullptr, nullptr, nullptr, nullptr, nullptr);

    // ---- join s1 back into s0 before returning (required for capture)
    cudaStreamWaitEvent(0, f1, 0);
}